// round 16
// baseline (speedup 1.0000x reference)
#include <cuda_runtime.h>
#include <cuda_fp16.h>
#include <math.h>
#include <stdint.h>

#define BDIM 8
#define HW 64
#define CMID 576
#define CCAT 1632
#define EPSV 1e-5f
#define NPASS 144

// conv smem geometry (fp16, chunk of 16 cin, M=256 tile -> 6 halo rows)
#define HALO_B (6 * 66 * 16 * 2)        // 12672 B
#define BT_B   (9 * 144 * 16 * 2)       // 41472 B
#define STG_B  (HALO_B + BT_B)          // 54144 B
#define NSTG   3
#define SMEM_BYTES (NSTG * STG_B)       // 162432 B

#define WT_SMEM (14688 * 4)
#define E1 2985984
#define E2 8460288
#define PSN ((size_t)BDIM * CMID * 4096)   // one split-K partial buffer

// ---------------------------------------------------------------------------
// Scratch (device globals)
// ---------------------------------------------------------------------------
__device__ __half g_cat1h[BDIM * 36 * 4096 * 16];
__device__ __half g_cat2h[BDIM * 102 * 4096 * 16];
__device__ __half g_midh [BDIM * 36 * 4096 * 16];
__device__ float  g_ps   [2 * BDIM * CMID * 4096];   // split-K partials
__device__ float  g_part [8 * BDIM * 4096];          // o1: 4 pass x 2 slice
__device__ float  g_small[BDIM * 4096];
__device__ __half g_wdh[E1];
__device__ __half g_wch[E2];
__device__ __half g_woh[E1];

// ---------------------------------------------------------------------------
// helpers
// ---------------------------------------------------------------------------
__device__ __forceinline__ uint32_t smem_u32(const void* p) {
    uint32_t a;
    asm("{ .reg .u64 t; cvta.to.shared.u64 t, %1; cvt.u32.u64 %0, t; }" : "=r"(a) : "l"(p));
    return a;
}
__device__ __forceinline__ void ldm_x4(uint32_t* r, uint32_t a) {
    asm volatile("ldmatrix.sync.aligned.m8n8.x4.shared.b16 {%0,%1,%2,%3}, [%4];"
                 : "=r"(r[0]), "=r"(r[1]), "=r"(r[2]), "=r"(r[3]) : "r"(a));
}
__device__ __forceinline__ void ldm_x2(uint32_t* r, uint32_t a) {
    asm volatile("ldmatrix.sync.aligned.m8n8.x2.shared.b16 {%0,%1}, [%2];"
                 : "=r"(r[0]), "=r"(r[1]) : "r"(a));
}
__device__ __forceinline__ void mma_f16(float* d, const uint32_t* a, uint32_t b0, uint32_t b1) {
    asm volatile("mma.sync.aligned.m16n8k16.row.col.f32.f16.f16.f32 "
        "{%0,%1,%2,%3}, {%4,%5,%6,%7}, {%8,%9}, {%0,%1,%2,%3};"
        : "+f"(d[0]), "+f"(d[1]), "+f"(d[2]), "+f"(d[3])
        : "r"(a[0]), "r"(a[1]), "r"(a[2]), "r"(a[3]), "r"(b0), "r"(b1));
}
__device__ __forceinline__ void cpa16(uint32_t dst, const void* src, uint32_t srcsz) {
    asm volatile("cp.async.cg.shared.global [%0], [%1], 16, %2;"
                 :: "r"(dst), "l"(src), "r"(srcsz) : "memory");
}
__device__ __forceinline__ void sts32z(uint32_t a) {
    asm volatile("st.shared.b32 [%0], %1;" :: "r"(a), "r"(0u) : "memory");
}

// ---------------------------------------------------------------------------
// prep_all: merged weight transform + input packing (independent work).
//   blocks [0, 1728)            : wtrans for (conv, cout)
//   blocks [1728, 1728+52224)   : pack_all block (b, ch, y)
// ---------------------------------------------------------------------------
#define WT_BLOCKS (3 * CMID)
__global__ void __launch_bounds__(256)
prep_all(const float* __restrict__ wd, const float* __restrict__ wc,
         const float* __restrict__ wo,
         __half* __restrict__ td, __half* __restrict__ tc, __half* __restrict__ to,
         const float* __restrict__ coarse, const float* __restrict__ x2,
         const float* __restrict__ x3, const float* __restrict__ raw,
         __half* __restrict__ cat1h, __half* __restrict__ cat2h) {
    extern __shared__ float s[];
    int tid = threadIdx.x;

    if (blockIdx.x < WT_BLOCKS) {
        // ---- weight transform: OIHW fp32 -> fp16 [ci-chunk16][pos][co][kl16]
        int co = blockIdx.x % CMID;
        int conv = blockIdx.x / CMID;
        const float* src; __half* dst; int Cin;
        if (conv == 0)      { src = wd; dst = td; Cin = 576; }
        else if (conv == 1) { src = wc; dst = tc; Cin = 1632; }
        else                { src = wo; dst = to; Cin = 576; }
        int n = Cin * 9;
        const float* row = src + (size_t)co * n;
        for (int i = tid; i < n; i += 256) s[i] = row[i];
        __syncthreads();
        int nu = (Cin >> 4) * 9;
        for (int u = tid; u < nu; u += 256) {
            int ch = u / 9;
            int pos = u - ch * 9;
            __half2* dp = (__half2*)(dst + ((size_t)u * CMID + co) * 16);
#pragma unroll
            for (int k2 = 0; k2 < 8; k2++) {
                float a = s[(ch * 16 + 2 * k2) * 9 + pos];
                float b = s[(ch * 16 + 2 * k2 + 1) * 9 + pos];
                dp[k2] = __floats2half2_rn(a, b);
            }
        }
        return;
    }

    // ---- pack: build cat1h / cat2h fp16 chunk-16 layout
    float (*sb)[65] = (float (*)[65])s;
    int id = blockIdx.x - WT_BLOCKS;
    int y = id & 63;
    int t = id >> 6;
    int ch = t % 102;
    int b = t / 102;

#pragma unroll
    for (int k = 0; k < 4; k++) {
        int e = tid + k * 256;
        int cl = e >> 6;
        int x = e & 63;
        float v;
        if (ch < 36) {
            int c = ch * 16 + cl;
            if (c < 384) {
                v = coarse[((b * 384 + c) << 12) + (y << 6) + x];
            } else {
                int pc = c - 384;
                int gy = pc / 24;
                int r  = pc - gy * 24;
                int gx = r / 3;
                int cc = r - gx * 3;
                v = raw[((b * 3 + cc) * 512 + gy * 64 + y) * 512 + gx * 64 + x];
            }
        } else if (ch < 84) {
            int c = (ch - 36) * 16 + cl;
            v = x2[((b * 768 + c) << 12) + (y << 6) + x];
        } else {
            int c = (ch - 84) * 16 + cl;
            v = x3[((b * 288 + c) << 12) + (y << 6) + x];
        }
        sb[cl][x] = v;
    }
    __syncthreads();

    __half* dstp;
    size_t base;
    if (ch < 36) {
        dstp = cat1h;
        base = (((size_t)(b * 36 + ch)) * 4096 + y * 64) * 16;
    } else {
        int c2 = (ch < 84) ? (ch - 36) : ch;
        dstp = cat2h;
        base = (((size_t)(b * 102 + c2)) * 4096 + y * 64) * 16;
    }
#pragma unroll
    for (int k = 0; k < 2; k++) {
        int w = tid + k * 256;
        int j0 = 2 * w;
        int cl = j0 & 15;
        int x = j0 >> 4;
        *(__half2*)(dstp + base + j0) = __floats2half2_rn(sb[cl][x], sb[cl + 1][x]);
    }
}

// ---------------------------------------------------------------------------
// conv3x3 (+BN), fp16 mma.m16n8k16 implicit GEMM, M=256 px tile. (R12 exact)
//   psum != null : raw fp32 partials -> psum[slice]          (cc split-K)
//   else outh    : BN + fp16 chunk-layout output             (dec)
//   else         : BN + fused conv1x1 -> part[pass*2+slice]  (o1 split-K)
// ---------------------------------------------------------------------------
__global__ void __launch_bounds__(256)
conv3x3_h(const __half* __restrict__ in, int Cin, int nch,
          const __half* __restrict__ wt,
          const float* __restrict__ gam, const float* __restrict__ bet,
          const float* __restrict__ mu,  const float* __restrict__ var,
          __half* __restrict__ outh, int CHT, int och_off,
          const float* __restrict__ w2, float* __restrict__ part,
          float* __restrict__ psum) {
    extern __shared__ char smc[];
    __shared__ float red[2][4][64];
    uint32_t smb = smem_u32(smc);

    int tid = threadIdx.x;
    int wid = tid >> 5;
    int lid = tid & 31;
    int l4 = lid >> 2;
    int kc = lid & 3;
    int mw = wid >> 1;
    int nw = wid & 1;

    int tile = blockIdx.x;
    int b  = tile >> 4;
    int y0 = (tile & 15) << 2;
    int pass = blockIdx.y;
    int cbase = pass * NPASS;
    int koff = blockIdx.z * nch;

    const char* inb = (const char*)(in + (size_t)b * Cin * 4096);
    const char* wtb = (const char*)wt;

    uint32_t hdst[3], hsrc[3], hsz[3];
#pragma unroll
    for (int i = 0; i < 3; i++) {
        int t = tid + i * 256;
        int row = t >> 7;
        int rem = t & 127;
        int x = rem >> 1;
        int seg = rem & 1;
        hdst[i] = (uint32_t)(((row * 66 + 1 + x) * 16 + seg * 8) * 2);
        int yg = y0 - 1 + row;
        int ok = (yg >= 0 && yg < 64);
        hsz[i] = ok ? 16u : 0u;
        hsrc[i] = (uint32_t)((((ok ? yg : 0) * 64 + x) * 16 + seg * 8) * 2)
                + (uint32_t)koff * 131072u;
    }
    uint32_t bdst[11], bsrc[11];
#pragma unroll
    for (int i = 0; i < 11; i++) {
        int t = tid + i * 256;
        if (t < 2592) {
            int pos = t / 288;
            int rem = t - pos * 288;
            int n = rem >> 1;
            int seg = rem & 1;
            bdst[i] = (uint32_t)(HALO_B + ((pos * 144 + n) * 16 + seg * 8) * 2);
            bsrc[i] = (uint32_t)((((pos * 576) + cbase + n) * 16 + seg * 8) * 2)
                    + (uint32_t)koff * 165888u;
        } else { bdst[i] = 0; bsrc[i] = 0; }
    }

    for (int e = tid; e < 288; e += 256) {
        int stg = e / 96;
        int rem = e - stg * 96;
        int row = rem >> 4;
        int rem2 = rem & 15;
        int side = rem2 >> 3;
        int w = rem2 & 7;
        sts32z(smb + (uint32_t)(stg * STG_B + ((row * 66 + (side ? 65 : 0)) * 16) * 2 + w * 4));
    }

    float d[4][9][4];
#pragma unroll
    for (int mi = 0; mi < 4; mi++)
#pragma unroll
        for (int ni = 0; ni < 9; ni++)
#pragma unroll
            for (int j = 0; j < 4; j++) d[mi][ni][j] = 0.f;

    auto issue = [&](int buf) {
        uint32_t sb0 = smb + (uint32_t)buf * STG_B;
#pragma unroll
        for (int i = 0; i < 3; i++) {
            cpa16(sb0 + hdst[i], inb + hsrc[i], hsz[i]);
            hsrc[i] += 4096u * 16u * 2u;
        }
#pragma unroll
        for (int i = 0; i < 11; i++) {
            if (i < 10 || tid < 32) {
                cpa16(sb0 + bdst[i], wtb + bsrc[i], 16u);
                bsrc[i] += 9u * 576u * 16u * 2u;
            }
        }
        asm volatile("cp.async.commit_group;" ::: "memory");
    };

    uint32_t xoffA = (uint32_t)((lid & 7) + (lid & 8));
    uint32_t khA   = (uint32_t)((lid >> 4) * 16);
    uint32_t noffB = (uint32_t)((lid & 7) + ((lid & 16) >> 1));
    uint32_t khB   = (uint32_t)(((lid >> 3) & 1) * 16);

    issue(0);
    issue(1);
    for (int ch = 0; ch < nch; ch++) {
        asm volatile("cp.async.wait_group 1;" ::: "memory");
        __syncthreads();

        uint32_t hb = smb + (uint32_t)(ch % NSTG) * STG_B;
        uint32_t bb = hb + HALO_B;
#pragma unroll
        for (int pos = 0; pos < 9; pos++) {
            const int ky = pos / 3, kx = pos % 3;
            uint32_t A[4][4];
            uint32_t pa = hb + (uint32_t)(((mw + ky) * 66 + kx) * 32) + xoffA * 32 + khA;
#pragma unroll
            for (int mi = 0; mi < 4; mi++)
                ldm_x4(A[mi], pa + (uint32_t)mi * 512);

            uint32_t pb = bb + (uint32_t)(pos * 4608) + (uint32_t)(nw * 72) * 32 + noffB * 32 + khB;
#pragma unroll
            for (int pp = 0; pp < 4; pp++) {
                uint32_t Bv[4];
                ldm_x4(Bv, pb + (uint32_t)pp * 512);
#pragma unroll
                for (int mi = 0; mi < 4; mi++) {
                    mma_f16(d[mi][2 * pp],     A[mi], Bv[0], Bv[1]);
                    mma_f16(d[mi][2 * pp + 1], A[mi], Bv[2], Bv[3]);
                }
            }
            {
                uint32_t pb8 = bb + (uint32_t)(pos * 4608) +
                               (uint32_t)((nw * 72 + 64 + (lid & 7)) * 32) + khB;
                uint32_t Bv[2];
                ldm_x2(Bv, pb8);
#pragma unroll
                for (int mi = 0; mi < 4; mi++)
                    mma_f16(d[mi][8], A[mi], Bv[0], Bv[1]);
            }
        }
        if (ch + 2 < nch) issue((ch + 2) % NSTG);
    }

    int row = y0 + mw;
    if (psum) {
        // ---- raw fp32 partials for split-K (no BN)  (cc)
        float* po = psum + (size_t)blockIdx.z * PSN + ((size_t)b * CMID << 12);
#pragma unroll
        for (int ni = 0; ni < 9; ni++) {
            int co0 = cbase + nw * 72 + ni * 8 + kc * 2;
            size_t p0 = ((size_t)co0 << 12) + (size_t)row * 64;
            size_t p1 = p0 + 4096;
#pragma unroll
            for (int mi = 0; mi < 4; mi++) {
                int x = mi * 16 + l4;
                po[p0 + x]     = d[mi][ni][0];
                po[p1 + x]     = d[mi][ni][1];
                po[p0 + x + 8] = d[mi][ni][2];
                po[p1 + x + 8] = d[mi][ni][3];
            }
        }
    } else if (outh) {
        // ---- BN + fp16 chunk-layout epilogue (dec)
#pragma unroll
        for (int ni = 0; ni < 9; ni++) {
            int co0 = cbase + nw * 72 + ni * 8 + kc * 2;
            int co1 = co0 + 1;
            float s0 = gam[co0] * rsqrtf(var[co0] + EPSV);
            float bi0 = bet[co0] - mu[co0] * s0;
            float s1 = gam[co1] * rsqrtf(var[co1] + EPSV);
            float bi1 = bet[co1] - mu[co1] * s1;
            int chn = (co0 >> 4) + och_off;
            int cl = co0 & 15;
            size_t basei = (((size_t)b * CHT + chn) * 4096 + row * 64) * 16 + cl;
#pragma unroll
            for (int mi = 0; mi < 4; mi++) {
                int x = mi * 16 + l4;
                *(__half2*)(outh + basei + (size_t)x * 16) =
                    __floats2half2_rn(d[mi][ni][0] * s0 + bi0, d[mi][ni][1] * s1 + bi1);
                *(__half2*)(outh + basei + (size_t)(x + 8) * 16) =
                    __floats2half2_rn(d[mi][ni][2] * s0 + bi0, d[mi][ni][3] * s1 + bi1);
            }
        }
    } else {
        // ---- fused conv1x1 epilogue (o1, split-K): bias only in slice 0
        float bgate = (blockIdx.z == 0) ? 1.f : 0.f;
        float pa[4], pb[4];
#pragma unroll
        for (int mi = 0; mi < 4; mi++) { pa[mi] = 0.f; pb[mi] = 0.f; }
#pragma unroll
        for (int ni = 0; ni < 9; ni++) {
            int co0 = cbase + nw * 72 + ni * 8 + kc * 2;
            int co1 = co0 + 1;
            float s0 = gam[co0] * rsqrtf(var[co0] + EPSV);
            float bi0 = (bet[co0] - mu[co0] * s0) * bgate;
            float s1 = gam[co1] * rsqrtf(var[co1] + EPSV);
            float bi1 = (bet[co1] - mu[co1] * s1) * bgate;
            float w20 = w2[co0];
            float w21 = w2[co1];
#pragma unroll
            for (int mi = 0; mi < 4; mi++) {
                pa[mi] += (d[mi][ni][0] * s0 + bi0) * w20 + (d[mi][ni][1] * s1 + bi1) * w21;
                pb[mi] += (d[mi][ni][2] * s0 + bi0) * w20 + (d[mi][ni][3] * s1 + bi1) * w21;
            }
        }
#pragma unroll
        for (int mi = 0; mi < 4; mi++) {
            pa[mi] += __shfl_xor_sync(0xffffffffu, pa[mi], 1);
            pa[mi] += __shfl_xor_sync(0xffffffffu, pa[mi], 2);
            pb[mi] += __shfl_xor_sync(0xffffffffu, pb[mi], 1);
            pb[mi] += __shfl_xor_sync(0xffffffffu, pb[mi], 2);
        }
        if (kc == 0) {
#pragma unroll
            for (int mi = 0; mi < 4; mi++) {
                red[nw][mw][mi * 16 + l4]     = pa[mi];
                red[nw][mw][mi * 16 + l4 + 8] = pb[mi];
            }
        }
        __syncthreads();
        int mwp = tid >> 6;
        int xp = tid & 63;
        part[(pass * 2 + blockIdx.z) * (BDIM * 4096) + (b << 12) + (y0 + mwp) * 64 + xp] =
            red[0][mwp][xp] + red[1][mwp][xp];
    }
}

// ---------------------------------------------------------------------------
// combine_cc: midh = fp16(BN(ps0 + ps1)), chunk-16 layout. (R12 exact)
// ---------------------------------------------------------------------------
__global__ void __launch_bounds__(256)
combine_cc(const float* __restrict__ ps,
           const float* __restrict__ gam, const float* __restrict__ bet,
           const float* __restrict__ mu,  const float* __restrict__ var,
           __half* __restrict__ midh) {
    __shared__ __half sb[256 * 17];
    __shared__ float ss[16], sbi[16];
    int id = blockIdx.x;
    int yt = id & 15;
    int t2 = id >> 4;
    int chn = t2 % 36;
    int b = t2 / 36;
    int tid = threadIdx.x;

    if (tid < 16) {
        int co = chn * 16 + tid;
        float s = gam[co] * rsqrtf(var[co] + EPSV);
        ss[tid] = s;
        sbi[tid] = bet[co] - mu[co] * s;
    }
    __syncthreads();

    int px0 = yt * 256;
#pragma unroll 4
    for (int e = tid; e < 4096; e += 256) {
        int co = e >> 8;
        int px = e & 255;
        size_t idx = (((size_t)(b * CMID + chn * 16 + co)) << 12) + px0 + px;
        float v = ps[idx] + ps[PSN + idx];
        sb[px * 17 + co] = __float2half_rn(v * ss[co] + sbi[co]);
    }
    __syncthreads();

    __half* dst = midh + (((size_t)(b * 36 + chn)) * 4096 + px0) * 16;
#pragma unroll 4
    for (int e = tid; e < 4096; e += 256)
        dst[e] = sb[(e >> 4) * 17 + (e & 15)];
}

// ---------------------------------------------------------------------------
// collapse: g_small = sum of 8 (pass,slice) partials + o2 bias (float4)
// ---------------------------------------------------------------------------
__global__ void collapse(const float* __restrict__ part,
                         const float* __restrict__ bias) {
    int i4 = blockIdx.x * 256 + threadIdx.x;
    if (i4 < BDIM * 1024) {
        const int N4 = BDIM * 1024;
        const float4* p = (const float4*)part;
        float4 a0 = p[i4],          a1 = p[N4 + i4];
        float4 a2 = p[2 * N4 + i4], a3 = p[3 * N4 + i4];
        float4 a4 = p[4 * N4 + i4], a5 = p[5 * N4 + i4];
        float4 a6 = p[6 * N4 + i4], a7 = p[7 * N4 + i4];
        float bz = bias[0];
        float4 r;
        r.x = ((a0.x + a1.x) + (a2.x + a3.x)) + ((a4.x + a5.x) + (a6.x + a7.x)) + bz;
        r.y = ((a0.y + a1.y) + (a2.y + a3.y)) + ((a4.y + a5.y) + (a6.y + a7.y)) + bz;
        r.z = ((a0.z + a1.z) + (a2.z + a3.z)) + ((a4.z + a5.z) + (a6.z + a7.z)) + bz;
        r.w = ((a0.w + a1.w) + (a2.w + a3.w)) + ((a4.w + a5.w) + (a6.w + a7.w)) + bz;
        ((float4*)g_small)[i4] = r;
    }
}

// ---------------------------------------------------------------------------
// bilinear x8 upsample (align_corners=True), 4 outputs/thread (float4 store)
// ---------------------------------------------------------------------------
__global__ void upsample8(float* __restrict__ out) {
    int q = blockIdx.x * blockDim.x + threadIdx.x;   // quad index
    if (q >= BDIM * 512 * 128) return;
    int qx = q & 127;
    int oy = (q >> 7) & 511;
    int b  = q >> 16;
    const float sc = 63.0f / 511.0f;
    float fy = (float)oy * sc;
    int y0 = (int)floorf(fy); int y1 = min(y0 + 1, 63);
    float wy = fy - (float)y0;
    const float* p = g_small + (b << 12);
    const float* r0p = p + y0 * 64;
    const float* r1p = p + y1 * 64;
    float4 r;
    float* rr = &r.x;
#pragma unroll
    for (int j = 0; j < 4; j++) {
        int ox = qx * 4 + j;
        float fx = (float)ox * sc;
        int x0 = (int)floorf(fx); int x1 = min(x0 + 1, 63);
        float wx = fx - (float)x0;
        float a0 = r0p[x0] * (1.f - wy) + r1p[x0] * wy;
        float a1 = r0p[x1] * (1.f - wy) + r1p[x1] * wy;
        rr[j] = a0 * (1.f - wx) + a1 * wx;
    }
    ((float4*)out)[q] = r;
}

// ---------------------------------------------------------------------------
extern "C" void kernel_launch(void* const* d_in, const int* in_sizes, int n_in,
                              void* d_out, int out_size) {
    const float* coarse = (const float*)d_in[0];
    const float* x2     = (const float*)d_in[1];
    const float* x3     = (const float*)d_in[2];
    const float* raw    = (const float*)d_in[3];
    const float* dec_w = (const float*)d_in[6];
    const float* dec_g = (const float*)d_in[7];
    const float* dec_b = (const float*)d_in[8];
    const float* dec_m = (const float*)d_in[9];
    const float* dec_v = (const float*)d_in[10];
    const float* cc_w  = (const float*)d_in[11];
    const float* cc_g  = (const float*)d_in[12];
    const float* cc_b  = (const float*)d_in[13];
    const float* cc_m  = (const float*)d_in[14];
    const float* cc_v  = (const float*)d_in[15];
    const float* o1_w  = (const float*)d_in[16];
    const float* o1_g  = (const float*)d_in[17];
    const float* o1_b  = (const float*)d_in[18];
    const float* o1_m  = (const float*)d_in[19];
    const float* o1_v  = (const float*)d_in[20];
    const float* o2_w  = (const float*)d_in[21];
    const float* o2_b  = (const float*)d_in[22];

    __half *cat1h, *cat2h, *midh, *wdh, *wch, *woh;
    float *partp, *psp;
    cudaGetSymbolAddress((void**)&cat1h, g_cat1h);
    cudaGetSymbolAddress((void**)&cat2h, g_cat2h);
    cudaGetSymbolAddress((void**)&midh,  g_midh);
    cudaGetSymbolAddress((void**)&partp, g_part);
    cudaGetSymbolAddress((void**)&psp,   g_ps);
    cudaGetSymbolAddress((void**)&wdh, g_wdh);
    cudaGetSymbolAddress((void**)&wch, g_wch);
    cudaGetSymbolAddress((void**)&woh, g_woh);

    cudaFuncSetAttribute(conv3x3_h,
                         cudaFuncAttributeMaxDynamicSharedMemorySize, SMEM_BYTES);
    cudaFuncSetAttribute(prep_all,
                         cudaFuncAttributeMaxDynamicSharedMemorySize, WT_SMEM);

    // merged weight transform + packing (independent blocks, one launch)
    prep_all<<<WT_BLOCKS + BDIM * 102 * 64, 256, WT_SMEM>>>(
        dec_w, cc_w, o1_w, wdh, wch, woh,
        coarse, x2, x3, raw, cat1h, cat2h);

    // dec: cat1h(576) -> cat2h chunks [48,84)   (grid 512, no split)
    conv3x3_h<<<dim3(128, 4, 1), 256, SMEM_BYTES>>>(cat1h, CMID, 36, wdh,
        dec_g, dec_b, dec_m, dec_v, cat2h, 102, 48, nullptr, nullptr, nullptr);
    // cc: cat2h(1632) -> split-K=2 fp32 partials (grid 1024)
    conv3x3_h<<<dim3(128, 4, 2), 256, SMEM_BYTES>>>(cat2h, CCAT, 51, wch,
        nullptr, nullptr, nullptr, nullptr, nullptr, 0, 0, nullptr, nullptr, psp);
    // combine partials -> BN -> midh fp16 chunk layout
    combine_cc<<<BDIM * 36 * 16, 256>>>(psp, cc_g, cc_b, cc_m, cc_v, midh);
    // o1 + fused conv1x1, split-K=2 -> 8 partial planes (grid 1024)
    conv3x3_h<<<dim3(128, 4, 2), 256, SMEM_BYTES>>>(midh, CMID, 18, woh,
        o1_g, o1_b, o1_m, o1_v, nullptr, 0, 0, o2_w, partp, nullptr);

    collapse<<<(BDIM * 1024 + 255) / 256, 256>>>(partp, o2_b);
    upsample8<<<(BDIM * 512 * 128 + 255) / 256, 256>>>((float*)d_out);
}

// round 17
// speedup vs baseline: 1.0719x; 1.0719x over previous
#include <cuda_runtime.h>
#include <cuda_fp16.h>
#include <math.h>
#include <stdint.h>

#define BDIM 8
#define HW 64
#define CMID 576
#define CCAT 1632
#define EPSV 1e-5f
#define NPASS 144

// conv smem geometry (fp16, chunk of 16 cin, M=256 tile -> 6 halo rows)
#define HALO_B (6 * 66 * 16 * 2)        // 12672 B
#define BT_B   (9 * 144 * 16 * 2)       // 41472 B
#define STG_B  (HALO_B + BT_B)          // 54144 B
#define NSTG   3
#define SMEM_BYTES (NSTG * STG_B)       // 162432 B

#define WT_SMEM (14688 * 4)
#define E1 2985984
#define E2 8460288
#define PSN ((size_t)BDIM * CMID * 4096)   // one split-K partial buffer

// ---------------------------------------------------------------------------
// Scratch (device globals)
// ---------------------------------------------------------------------------
__device__ __half g_cat1h[BDIM * 36 * 4096 * 16];
__device__ __half g_cat2h[BDIM * 102 * 4096 * 16];
__device__ __half g_midh [BDIM * 36 * 4096 * 16];
__device__ float  g_ps   [2 * BDIM * CMID * 4096];   // split-K partials
__device__ float  g_part [8 * BDIM * 4096];          // o1: 4 pass x 2 slice
__device__ float  g_small[BDIM * 4096];
__device__ __half g_wdh[E1];
__device__ __half g_wch[E2];
__device__ __half g_woh[E1];

// ---------------------------------------------------------------------------
// helpers
// ---------------------------------------------------------------------------
__device__ __forceinline__ uint32_t smem_u32(const void* p) {
    uint32_t a;
    asm("{ .reg .u64 t; cvta.to.shared.u64 t, %1; cvt.u32.u64 %0, t; }" : "=r"(a) : "l"(p));
    return a;
}
__device__ __forceinline__ void ldm_x4(uint32_t* r, uint32_t a) {
    asm volatile("ldmatrix.sync.aligned.m8n8.x4.shared.b16 {%0,%1,%2,%3}, [%4];"
                 : "=r"(r[0]), "=r"(r[1]), "=r"(r[2]), "=r"(r[3]) : "r"(a));
}
__device__ __forceinline__ void ldm_x2(uint32_t* r, uint32_t a) {
    asm volatile("ldmatrix.sync.aligned.m8n8.x2.shared.b16 {%0,%1}, [%2];"
                 : "=r"(r[0]), "=r"(r[1]) : "r"(a));
}
__device__ __forceinline__ void mma_f16(float* d, const uint32_t* a, uint32_t b0, uint32_t b1) {
    asm volatile("mma.sync.aligned.m16n8k16.row.col.f32.f16.f16.f32 "
        "{%0,%1,%2,%3}, {%4,%5,%6,%7}, {%8,%9}, {%0,%1,%2,%3};"
        : "+f"(d[0]), "+f"(d[1]), "+f"(d[2]), "+f"(d[3])
        : "r"(a[0]), "r"(a[1]), "r"(a[2]), "r"(a[3]), "r"(b0), "r"(b1));
}
__device__ __forceinline__ void cpa16(uint32_t dst, const void* src, uint32_t srcsz) {
    asm volatile("cp.async.cg.shared.global [%0], [%1], 16, %2;"
                 :: "r"(dst), "l"(src), "r"(srcsz) : "memory");
}
__device__ __forceinline__ void sts32z(uint32_t a) {
    asm volatile("st.shared.b32 [%0], %1;" :: "r"(a), "r"(0u) : "memory");
}

// ---------------------------------------------------------------------------
// Coalesced weight transform: one block per (conv, cout).
// OIHW fp32 -> fp16 [ci-chunk16][pos][co][kl16]
// ---------------------------------------------------------------------------
__global__ void __launch_bounds__(256)
wtrans2(const float* __restrict__ wd, const float* __restrict__ wc,
        const float* __restrict__ wo,
        __half* __restrict__ td, __half* __restrict__ tc, __half* __restrict__ to) {
    extern __shared__ float s[];
    int co = blockIdx.x % CMID;
    int conv = blockIdx.x / CMID;
    const float* src; __half* dst; int Cin;
    if (conv == 0)      { src = wd; dst = td; Cin = 576; }
    else if (conv == 1) { src = wc; dst = tc; Cin = 1632; }
    else                { src = wo; dst = to; Cin = 576; }
    int n = Cin * 9;
    const float* row = src + (size_t)co * n;
    int tid = threadIdx.x;
    for (int i = tid; i < n; i += 256) s[i] = row[i];
    __syncthreads();
    int nu = (Cin >> 4) * 9;
    for (int u = tid; u < nu; u += 256) {
        int ch = u / 9;
        int pos = u - ch * 9;
        __half2* dp = (__half2*)(dst + ((size_t)u * CMID + co) * 16);
#pragma unroll
        for (int k2 = 0; k2 < 8; k2++) {
            float a = s[(ch * 16 + 2 * k2) * 9 + pos];
            float b = s[(ch * 16 + 2 * k2 + 1) * 9 + pos];
            dp[k2] = __floats2half2_rn(a, b);
        }
    }
}

// ---------------------------------------------------------------------------
// pack_all: build cat1h (36 chunks) and cat2h side chunks, fp16 chunk-16.
// ---------------------------------------------------------------------------
__global__ void __launch_bounds__(256)
pack_all(const float* __restrict__ coarse, const float* __restrict__ x2,
         const float* __restrict__ x3, const float* __restrict__ raw,
         __half* __restrict__ cat1h, __half* __restrict__ cat2h) {
    __shared__ float sb[16][65];
    int id = blockIdx.x;
    int y = id & 63;
    int t = id >> 6;
    int ch = t % 102;
    int b = t / 102;
    int tid = threadIdx.x;

#pragma unroll
    for (int k = 0; k < 4; k++) {
        int e = tid + k * 256;
        int cl = e >> 6;
        int x = e & 63;
        float v;
        if (ch < 36) {
            int c = ch * 16 + cl;
            if (c < 384) {
                v = coarse[((b * 384 + c) << 12) + (y << 6) + x];
            } else {
                int pc = c - 384;
                int gy = pc / 24;
                int r  = pc - gy * 24;
                int gx = r / 3;
                int cc = r - gx * 3;
                v = raw[((b * 3 + cc) * 512 + gy * 64 + y) * 512 + gx * 64 + x];
            }
        } else if (ch < 84) {
            int c = (ch - 36) * 16 + cl;
            v = x2[((b * 768 + c) << 12) + (y << 6) + x];
        } else {
            int c = (ch - 84) * 16 + cl;
            v = x3[((b * 288 + c) << 12) + (y << 6) + x];
        }
        sb[cl][x] = v;
    }
    __syncthreads();

    __half* dstp;
    size_t base;
    if (ch < 36) {
        dstp = cat1h;
        base = (((size_t)(b * 36 + ch)) * 4096 + y * 64) * 16;
    } else {
        int c2 = (ch < 84) ? (ch - 36) : ch;
        dstp = cat2h;
        base = (((size_t)(b * 102 + c2)) * 4096 + y * 64) * 16;
    }
#pragma unroll
    for (int k = 0; k < 2; k++) {
        int w = tid + k * 256;
        int j0 = 2 * w;
        int cl = j0 & 15;
        int x = j0 >> 4;
        *(__half2*)(dstp + base + j0) = __floats2half2_rn(sb[cl][x], sb[cl + 1][x]);
    }
}

// ---------------------------------------------------------------------------
// conv3x3 (+BN), fp16 mma.m16n8k16 implicit GEMM, M=256 px tile. (R12 exact)
//   psum != null : raw fp32 partials -> psum[slice]          (cc split-K)
//   else outh    : BN + fp16 chunk-layout output             (dec)
//   else         : BN + fused conv1x1 -> part[pass*2+slice]  (o1 split-K)
// ---------------------------------------------------------------------------
__global__ void __launch_bounds__(256)
conv3x3_h(const __half* __restrict__ in, int Cin, int nch,
          const __half* __restrict__ wt,
          const float* __restrict__ gam, const float* __restrict__ bet,
          const float* __restrict__ mu,  const float* __restrict__ var,
          __half* __restrict__ outh, int CHT, int och_off,
          const float* __restrict__ w2, float* __restrict__ part,
          float* __restrict__ psum) {
    extern __shared__ char smc[];
    __shared__ float red[2][4][64];
    uint32_t smb = smem_u32(smc);

    int tid = threadIdx.x;
    int wid = tid >> 5;
    int lid = tid & 31;
    int l4 = lid >> 2;
    int kc = lid & 3;
    int mw = wid >> 1;
    int nw = wid & 1;

    int tile = blockIdx.x;
    int b  = tile >> 4;
    int y0 = (tile & 15) << 2;
    int pass = blockIdx.y;
    int cbase = pass * NPASS;
    int koff = blockIdx.z * nch;

    const char* inb = (const char*)(in + (size_t)b * Cin * 4096);
    const char* wtb = (const char*)wt;

    uint32_t hdst[3], hsrc[3], hsz[3];
#pragma unroll
    for (int i = 0; i < 3; i++) {
        int t = tid + i * 256;
        int row = t >> 7;
        int rem = t & 127;
        int x = rem >> 1;
        int seg = rem & 1;
        hdst[i] = (uint32_t)(((row * 66 + 1 + x) * 16 + seg * 8) * 2);
        int yg = y0 - 1 + row;
        int ok = (yg >= 0 && yg < 64);
        hsz[i] = ok ? 16u : 0u;
        hsrc[i] = (uint32_t)((((ok ? yg : 0) * 64 + x) * 16 + seg * 8) * 2)
                + (uint32_t)koff * 131072u;
    }
    uint32_t bdst[11], bsrc[11];
#pragma unroll
    for (int i = 0; i < 11; i++) {
        int t = tid + i * 256;
        if (t < 2592) {
            int pos = t / 288;
            int rem = t - pos * 288;
            int n = rem >> 1;
            int seg = rem & 1;
            bdst[i] = (uint32_t)(HALO_B + ((pos * 144 + n) * 16 + seg * 8) * 2);
            bsrc[i] = (uint32_t)((((pos * 576) + cbase + n) * 16 + seg * 8) * 2)
                    + (uint32_t)koff * 165888u;
        } else { bdst[i] = 0; bsrc[i] = 0; }
    }

    for (int e = tid; e < 288; e += 256) {
        int stg = e / 96;
        int rem = e - stg * 96;
        int row = rem >> 4;
        int rem2 = rem & 15;
        int side = rem2 >> 3;
        int w = rem2 & 7;
        sts32z(smb + (uint32_t)(stg * STG_B + ((row * 66 + (side ? 65 : 0)) * 16) * 2 + w * 4));
    }

    float d[4][9][4];
#pragma unroll
    for (int mi = 0; mi < 4; mi++)
#pragma unroll
        for (int ni = 0; ni < 9; ni++)
#pragma unroll
            for (int j = 0; j < 4; j++) d[mi][ni][j] = 0.f;

    auto issue = [&](int buf) {
        uint32_t sb0 = smb + (uint32_t)buf * STG_B;
#pragma unroll
        for (int i = 0; i < 3; i++) {
            cpa16(sb0 + hdst[i], inb + hsrc[i], hsz[i]);
            hsrc[i] += 4096u * 16u * 2u;
        }
#pragma unroll
        for (int i = 0; i < 11; i++) {
            if (i < 10 || tid < 32) {
                cpa16(sb0 + bdst[i], wtb + bsrc[i], 16u);
                bsrc[i] += 9u * 576u * 16u * 2u;
            }
        }
        asm volatile("cp.async.commit_group;" ::: "memory");
    };

    uint32_t xoffA = (uint32_t)((lid & 7) + (lid & 8));
    uint32_t khA   = (uint32_t)((lid >> 4) * 16);
    uint32_t noffB = (uint32_t)((lid & 7) + ((lid & 16) >> 1));
    uint32_t khB   = (uint32_t)(((lid >> 3) & 1) * 16);

    issue(0);
    issue(1);
    for (int ch = 0; ch < nch; ch++) {
        asm volatile("cp.async.wait_group 1;" ::: "memory");
        __syncthreads();

        uint32_t hb = smb + (uint32_t)(ch % NSTG) * STG_B;
        uint32_t bb = hb + HALO_B;
#pragma unroll
        for (int pos = 0; pos < 9; pos++) {
            const int ky = pos / 3, kx = pos % 3;
            uint32_t A[4][4];
            uint32_t pa = hb + (uint32_t)(((mw + ky) * 66 + kx) * 32) + xoffA * 32 + khA;
#pragma unroll
            for (int mi = 0; mi < 4; mi++)
                ldm_x4(A[mi], pa + (uint32_t)mi * 512);

            uint32_t pb = bb + (uint32_t)(pos * 4608) + (uint32_t)(nw * 72) * 32 + noffB * 32 + khB;
#pragma unroll
            for (int pp = 0; pp < 4; pp++) {
                uint32_t Bv[4];
                ldm_x4(Bv, pb + (uint32_t)pp * 512);
#pragma unroll
                for (int mi = 0; mi < 4; mi++) {
                    mma_f16(d[mi][2 * pp],     A[mi], Bv[0], Bv[1]);
                    mma_f16(d[mi][2 * pp + 1], A[mi], Bv[2], Bv[3]);
                }
            }
            {
                uint32_t pb8 = bb + (uint32_t)(pos * 4608) +
                               (uint32_t)((nw * 72 + 64 + (lid & 7)) * 32) + khB;
                uint32_t Bv[2];
                ldm_x2(Bv, pb8);
#pragma unroll
                for (int mi = 0; mi < 4; mi++)
                    mma_f16(d[mi][8], A[mi], Bv[0], Bv[1]);
            }
        }
        if (ch + 2 < nch) issue((ch + 2) % NSTG);
    }

    int row = y0 + mw;
    if (psum) {
        // ---- raw fp32 partials for split-K (no BN)  (cc)
        float* po = psum + (size_t)blockIdx.z * PSN + ((size_t)b * CMID << 12);
#pragma unroll
        for (int ni = 0; ni < 9; ni++) {
            int co0 = cbase + nw * 72 + ni * 8 + kc * 2;
            size_t p0 = ((size_t)co0 << 12) + (size_t)row * 64;
            size_t p1 = p0 + 4096;
#pragma unroll
            for (int mi = 0; mi < 4; mi++) {
                int x = mi * 16 + l4;
                po[p0 + x]     = d[mi][ni][0];
                po[p1 + x]     = d[mi][ni][1];
                po[p0 + x + 8] = d[mi][ni][2];
                po[p1 + x + 8] = d[mi][ni][3];
            }
        }
    } else if (outh) {
        // ---- BN + fp16 chunk-layout epilogue (dec)
#pragma unroll
        for (int ni = 0; ni < 9; ni++) {
            int co0 = cbase + nw * 72 + ni * 8 + kc * 2;
            int co1 = co0 + 1;
            float s0 = gam[co0] * rsqrtf(var[co0] + EPSV);
            float bi0 = bet[co0] - mu[co0] * s0;
            float s1 = gam[co1] * rsqrtf(var[co1] + EPSV);
            float bi1 = bet[co1] - mu[co1] * s1;
            int chn = (co0 >> 4) + och_off;
            int cl = co0 & 15;
            size_t basei = (((size_t)b * CHT + chn) * 4096 + row * 64) * 16 + cl;
#pragma unroll
            for (int mi = 0; mi < 4; mi++) {
                int x = mi * 16 + l4;
                *(__half2*)(outh + basei + (size_t)x * 16) =
                    __floats2half2_rn(d[mi][ni][0] * s0 + bi0, d[mi][ni][1] * s1 + bi1);
                *(__half2*)(outh + basei + (size_t)(x + 8) * 16) =
                    __floats2half2_rn(d[mi][ni][2] * s0 + bi0, d[mi][ni][3] * s1 + bi1);
            }
        }
    } else {
        // ---- fused conv1x1 epilogue (o1, split-K): bias only in slice 0
        float bgate = (blockIdx.z == 0) ? 1.f : 0.f;
        float pa[4], pb[4];
#pragma unroll
        for (int mi = 0; mi < 4; mi++) { pa[mi] = 0.f; pb[mi] = 0.f; }
#pragma unroll
        for (int ni = 0; ni < 9; ni++) {
            int co0 = cbase + nw * 72 + ni * 8 + kc * 2;
            int co1 = co0 + 1;
            float s0 = gam[co0] * rsqrtf(var[co0] + EPSV);
            float bi0 = (bet[co0] - mu[co0] * s0) * bgate;
            float s1 = gam[co1] * rsqrtf(var[co1] + EPSV);
            float bi1 = (bet[co1] - mu[co1] * s1) * bgate;
            float w20 = w2[co0];
            float w21 = w2[co1];
#pragma unroll
            for (int mi = 0; mi < 4; mi++) {
                pa[mi] += (d[mi][ni][0] * s0 + bi0) * w20 + (d[mi][ni][1] * s1 + bi1) * w21;
                pb[mi] += (d[mi][ni][2] * s0 + bi0) * w20 + (d[mi][ni][3] * s1 + bi1) * w21;
            }
        }
#pragma unroll
        for (int mi = 0; mi < 4; mi++) {
            pa[mi] += __shfl_xor_sync(0xffffffffu, pa[mi], 1);
            pa[mi] += __shfl_xor_sync(0xffffffffu, pa[mi], 2);
            pb[mi] += __shfl_xor_sync(0xffffffffu, pb[mi], 1);
            pb[mi] += __shfl_xor_sync(0xffffffffu, pb[mi], 2);
        }
        if (kc == 0) {
#pragma unroll
            for (int mi = 0; mi < 4; mi++) {
                red[nw][mw][mi * 16 + l4]     = pa[mi];
                red[nw][mw][mi * 16 + l4 + 8] = pb[mi];
            }
        }
        __syncthreads();
        int mwp = tid >> 6;
        int xp = tid & 63;
        part[(pass * 2 + blockIdx.z) * (BDIM * 4096) + (b << 12) + (y0 + mwp) * 64 + xp] =
            red[0][mwp][xp] + red[1][mwp][xp];
    }
}

// ---------------------------------------------------------------------------
// combine_cc: midh = fp16(BN(ps0 + ps1)), chunk-16 layout. float4 loads.
// ---------------------------------------------------------------------------
__global__ void __launch_bounds__(256)
combine_cc(const float* __restrict__ ps,
           const float* __restrict__ gam, const float* __restrict__ bet,
           const float* __restrict__ mu,  const float* __restrict__ var,
           __half* __restrict__ midh) {
    __shared__ __half sb[256 * 17];
    __shared__ float ss[16], sbi[16];
    int id = blockIdx.x;
    int yt = id & 15;
    int t2 = id >> 4;
    int chn = t2 % 36;
    int b = t2 / 36;
    int tid = threadIdx.x;

    if (tid < 16) {
        int co = chn * 16 + tid;
        float s = gam[co] * rsqrtf(var[co] + EPSV);
        ss[tid] = s;
        sbi[tid] = bet[co] - mu[co] * s;
    }
    __syncthreads();

    int px0 = yt * 256;
    const float4* ps4 = (const float4*)ps;
    const size_t PSN4 = PSN >> 2;
#pragma unroll
    for (int e4 = tid; e4 < 1024; e4 += 256) {
        int co = e4 >> 6;
        int px = (e4 & 63) * 4;
        size_t idx4 = ((((size_t)(b * CMID + chn * 16 + co)) << 12) + px0 + px) >> 2;
        float4 v0 = ps4[idx4];
        float4 v1 = ps4[PSN4 + idx4];
        float s = ss[co], bi = sbi[co];
        sb[(px + 0) * 17 + co] = __float2half_rn((v0.x + v1.x) * s + bi);
        sb[(px + 1) * 17 + co] = __float2half_rn((v0.y + v1.y) * s + bi);
        sb[(px + 2) * 17 + co] = __float2half_rn((v0.z + v1.z) * s + bi);
        sb[(px + 3) * 17 + co] = __float2half_rn((v0.w + v1.w) * s + bi);
    }
    __syncthreads();

    __half* dst = midh + (((size_t)(b * 36 + chn)) * 4096 + px0) * 16;
#pragma unroll 4
    for (int e = tid; e < 4096; e += 256)
        dst[e] = sb[(e >> 4) * 17 + (e & 15)];
}

// ---------------------------------------------------------------------------
// collapse: g_small = sum of 8 (pass,slice) partials + o2 bias (float4)
// ---------------------------------------------------------------------------
__global__ void collapse(const float* __restrict__ part,
                         const float* __restrict__ bias) {
    int i4 = blockIdx.x * 256 + threadIdx.x;
    if (i4 < BDIM * 1024) {
        const int N4 = BDIM * 1024;
        const float4* p = (const float4*)part;
        float4 a0 = p[i4],          a1 = p[N4 + i4];
        float4 a2 = p[2 * N4 + i4], a3 = p[3 * N4 + i4];
        float4 a4 = p[4 * N4 + i4], a5 = p[5 * N4 + i4];
        float4 a6 = p[6 * N4 + i4], a7 = p[7 * N4 + i4];
        float bz = bias[0];
        float4 r;
        r.x = ((a0.x + a1.x) + (a2.x + a3.x)) + ((a4.x + a5.x) + (a6.x + a7.x)) + bz;
        r.y = ((a0.y + a1.y) + (a2.y + a3.y)) + ((a4.y + a5.y) + (a6.y + a7.y)) + bz;
        r.z = ((a0.z + a1.z) + (a2.z + a3.z)) + ((a4.z + a5.z) + (a6.z + a7.z)) + bz;
        r.w = ((a0.w + a1.w) + (a2.w + a3.w)) + ((a4.w + a5.w) + (a6.w + a7.w)) + bz;
        ((float4*)g_small)[i4] = r;
    }
}

// ---------------------------------------------------------------------------
// bilinear x8 upsample (align_corners=True), 4 outputs/thread (float4 store)
// ---------------------------------------------------------------------------
__global__ void upsample8(float* __restrict__ out) {
    int q = blockIdx.x * blockDim.x + threadIdx.x;   // quad index
    if (q >= BDIM * 512 * 128) return;
    int qx = q & 127;
    int oy = (q >> 7) & 511;
    int b  = q >> 16;
    const float sc = 63.0f / 511.0f;
    float fy = (float)oy * sc;
    int y0 = (int)floorf(fy); int y1 = min(y0 + 1, 63);
    float wy = fy - (float)y0;
    const float* p = g_small + (b << 12);
    const float* r0p = p + y0 * 64;
    const float* r1p = p + y1 * 64;
    float4 r;
    float* rr = &r.x;
#pragma unroll
    for (int j = 0; j < 4; j++) {
        int ox = qx * 4 + j;
        float fx = (float)ox * sc;
        int x0 = (int)floorf(fx); int x1 = min(x0 + 1, 63);
        float wx = fx - (float)x0;
        float a0 = r0p[x0] * (1.f - wy) + r1p[x0] * wy;
        float a1 = r0p[x1] * (1.f - wy) + r1p[x1] * wy;
        rr[j] = a0 * (1.f - wx) + a1 * wx;
    }
    ((float4*)out)[q] = r;
}

// ---------------------------------------------------------------------------
extern "C" void kernel_launch(void* const* d_in, const int* in_sizes, int n_in,
                              void* d_out, int out_size) {
    const float* coarse = (const float*)d_in[0];
    const float* x2     = (const float*)d_in[1];
    const float* x3     = (const float*)d_in[2];
    const float* raw    = (const float*)d_in[3];
    const float* dec_w = (const float*)d_in[6];
    const float* dec_g = (const float*)d_in[7];
    const float* dec_b = (const float*)d_in[8];
    const float* dec_m = (const float*)d_in[9];
    const float* dec_v = (const float*)d_in[10];
    const float* cc_w  = (const float*)d_in[11];
    const float* cc_g  = (const float*)d_in[12];
    const float* cc_b  = (const float*)d_in[13];
    const float* cc_m  = (const float*)d_in[14];
    const float* cc_v  = (const float*)d_in[15];
    const float* o1_w  = (const float*)d_in[16];
    const float* o1_g  = (const float*)d_in[17];
    const float* o1_b  = (const float*)d_in[18];
    const float* o1_m  = (const float*)d_in[19];
    const float* o1_v  = (const float*)d_in[20];
    const float* o2_w  = (const float*)d_in[21];
    const float* o2_b  = (const float*)d_in[22];

    __half *cat1h, *cat2h, *midh, *wdh, *wch, *woh;
    float *partp, *psp;
    cudaGetSymbolAddress((void**)&cat1h, g_cat1h);
    cudaGetSymbolAddress((void**)&cat2h, g_cat2h);
    cudaGetSymbolAddress((void**)&midh,  g_midh);
    cudaGetSymbolAddress((void**)&partp, g_part);
    cudaGetSymbolAddress((void**)&psp,   g_ps);
    cudaGetSymbolAddress((void**)&wdh, g_wdh);
    cudaGetSymbolAddress((void**)&wch, g_wch);
    cudaGetSymbolAddress((void**)&woh, g_woh);

    cudaFuncSetAttribute(conv3x3_h,
                         cudaFuncAttributeMaxDynamicSharedMemorySize, SMEM_BYTES);
    cudaFuncSetAttribute(wtrans2,
                         cudaFuncAttributeMaxDynamicSharedMemorySize, WT_SMEM);

    wtrans2<<<3 * CMID, 256, WT_SMEM>>>(dec_w, cc_w, o1_w, wdh, wch, woh);
    pack_all<<<BDIM * 102 * 64, 256>>>(coarse, x2, x3, raw, cat1h, cat2h);

    // dec: cat1h(576) -> cat2h chunks [48,84)   (grid 512, no split)
    conv3x3_h<<<dim3(128, 4, 1), 256, SMEM_BYTES>>>(cat1h, CMID, 36, wdh,
        dec_g, dec_b, dec_m, dec_v, cat2h, 102, 48, nullptr, nullptr, nullptr);
    // cc: cat2h(1632) -> split-K=2 fp32 partials (grid 1024)
    conv3x3_h<<<dim3(128, 4, 2), 256, SMEM_BYTES>>>(cat2h, CCAT, 51, wch,
        nullptr, nullptr, nullptr, nullptr, nullptr, 0, 0, nullptr, nullptr, psp);
    // combine partials -> BN -> midh fp16 chunk layout
    combine_cc<<<BDIM * 36 * 16, 256>>>(psp, cc_g, cc_b, cc_m, cc_v, midh);
    // o1 + fused conv1x1, split-K=2 -> 8 partial planes (grid 1024)
    conv3x3_h<<<dim3(128, 4, 2), 256, SMEM_BYTES>>>(midh, CMID, 18, woh,
        o1_g, o1_b, o1_m, o1_v, nullptr, 0, 0, o2_w, partp, nullptr);

    collapse<<<(BDIM * 1024 + 255) / 256, 256>>>(partp, o2_b);
    upsample8<<<(BDIM * 512 * 128 + 255) / 256, 256>>>((float*)d_out);
}